// round 10
// baseline (speedup 1.0000x reference)
#include <cuda_runtime.h>

// KMeansProbSampler: 8 iterations of weighted k-means scatter on a 1024x1024
// heatmap with 128 clusters.
//
// R10 = R9 with the per-CTA fixed cost amortized:
//   - grid 512, each CTA processes 2 adjacent 32x32 tiles (one pos load,
//     one sacc, 2 block barriers, one global flush per CTA instead of two),
//   - heat LDG hoisted to the top of each tile section (latency overlaps
//     prune/compact),
//   - warp-uniform nsurv==1 fast path skips the per-pixel scan,
//   - survivor scan unrolled x2 (s0 compared before s1 -> ascending strict
//     '<' tie order preserved).
//
// Math core (unchanged, rel_err ~2e-4):
//   key_k(r,c) = fmaf(c, -2cc_k, fmaf(r, -2cr_k, n_k)), n_k = cr^2+cc^2
//   (shifted squared distance; argmin-invariant shift; linear in r,c and fma
//   is correctly rounded -> rectangle min/max at the 4 corners with the
//   identical fmaf composition as the scan).
// Per warp (8x16 sub-tile): corner keys per cluster, UB = min_k max_corner,
//   keep k iff min_corner <= UB (winner+ties always kept), ballot-compact
//   ascending; per-pixel scan strict '<' ascending (lowest index on ties =
//   argmin). Exact d2 for winner; w = h*min(1,rsqrt(d2)). Run-combined
//   shared atomics; per-CTA flush into 1 of 16 partial buffers.

#define HH 1024
#define WW 1024
#define CC 128
#define NITER 8
#define PX 4
#define TPB 256
#define NWARP (TPB / 32)
#define BT 32
#define NPART 16
#define TILES_PER_CTA 2
#define GRID ((HH / BT) * (WW / BT) / TILES_PER_CTA)   // 512

__device__ float g_part[2][NPART][CC * 2];   // double-buffered partial sums
__device__ float g_pos[CC * 2];              // reduced positions for this iter

// prep: pos <- reduce(src over npart buffers); zero the partials at `zp`
__global__ void prep_kernel(const float* __restrict__ src, int npart,
                            float* __restrict__ pos, float* __restrict__ zp)
{
    const int t = threadIdx.x;          // 256 threads
    float s = 0.0f;
    for (int p = 0; p < npart; p++) s += src[p * (CC * 2) + t];
    pos[t] = s;
    float4* z4 = reinterpret_cast<float4*>(zp);
#pragma unroll
    for (int i = 0; i < NPART * (CC * 2) / 4 / TPB; i++)
        z4[i * TPB + t] = make_float4(0.f, 0.f, 0.f, 0.f);
}

__global__ void final_kernel(const float* __restrict__ src,
                             float* __restrict__ out)
{
    const int t = threadIdx.x;
    float s = 0.0f;
#pragma unroll
    for (int p = 0; p < NPART; p++) s += src[p * (CC * 2) + t];
    out[t] = s;
}

__global__ __launch_bounds__(TPB) void kmeans_iter_kernel(
    const float* __restrict__ pos_in,     // [C*2] current positions
    const float* __restrict__ heat,       // [H,W]
    float* __restrict__ part)             // [NPART][C*2] scatter target (zeroed)
{
    __shared__ __align__(16) float4 sh_surv[NWARP][CC];  // (n,-2cr,-2cc,idx)
    __shared__ float2 sh_pos[CC];                        // (cr, cc)
    __shared__ float  sacc[CC * 2];

    const int t    = threadIdx.x;
    const int w    = t >> 5;
    const int lane = t & 31;

    if (t < CC) {
        sh_pos[t] = make_float2(pos_in[2 * t], pos_in[2 * t + 1]);
    }
    sacc[t] = 0.0f;
    __syncthreads();

#pragma unroll
    for (int sub = 0; sub < TILES_PER_CTA; sub++) {
        const int tile = blockIdx.x * TILES_PER_CTA + sub;
        const int ty   = tile >> 5;
        const int tx   = tile & 31;
        const int wr0  = (ty << 5) + ((w >> 1) << 3);   // warp 8x16 sub-tile
        const int wc0  = (tx << 5) + ((w & 1) << 4);
        const int   prow = wr0 + (lane >> 2);
        const int   pcol = wc0 + ((lane & 3) << 2);
        const float rf   = (float)prow;

        // hoist heat load: DRAM/L2 latency overlaps prune + compact
        const float4 hv = *reinterpret_cast<const float4*>(heat + prow * WW + pcol);

        // ---- per-warp 2D pruning: 4 clusters per lane ----
        const float rLo = (float)wr0, rHi = (float)(wr0 + 7);
        const float cLo = (float)wc0, cHi = (float)(wc0 + 15);

        float3 cl[4];
        float  mn[4];
        float  ubl = 3.4e38f;
#pragma unroll
        for (int q = 0; q < 4; q++) {
            float2 p   = sh_pos[lane + 32 * q];
            float  n   = fmaf(p.x, p.x, p.y * p.y);
            float  m2r = -2.0f * p.x;
            float  m2c = -2.0f * p.y;
            cl[q] = make_float3(n, m2r, m2c);
            float bLo = fmaf(rLo, m2r, n);
            float bHi = fmaf(rHi, m2r, n);
            float k00 = fmaf(cLo, m2c, bLo);
            float k01 = fmaf(cHi, m2c, bLo);
            float k10 = fmaf(cLo, m2c, bHi);
            float k11 = fmaf(cHi, m2c, bHi);
            mn[q]    = fminf(fminf(k00, k01), fminf(k10, k11));
            float mx = fmaxf(fmaxf(k00, k01), fmaxf(k10, k11));
            ubl = fminf(ubl, mx);
        }
        float ub = ubl;
#pragma unroll
        for (int off = 16; off; off >>= 1)
            ub = fminf(ub, __shfl_xor_sync(0xffffffffu, ub, off));

        int base = 0;
#pragma unroll
        for (int q = 0; q < 4; q++) {             // ascending q, ascending lane
            bool     p   = (mn[q] <= ub);         // non-strict: ties survive
            unsigned bal = __ballot_sync(0xffffffffu, p);
            int      pos = base + __popc(bal & ((1u << lane) - 1u));
            if (p) {
                sh_surv[w][pos] = make_float4(cl[q].x, cl[q].y, cl[q].z,
                                              __int_as_float(lane + 32 * q));
            }
            base += __popc(bal);
        }
        const int nsurv = base;
        __syncwarp();

        const float cf0 = (float)pcol;
        const float cfs[PX] = {cf0, cf0 + 1.0f, cf0 + 2.0f, cf0 + 3.0f};
        const float heats[PX] = {hv.x, hv.y, hv.z, hv.w};

        int bests[PX];
        if (nsurv == 1) {
            // warp-uniform fast path: single survivor wins every pixel
            const int bi = __float_as_int(sh_surv[w][0].w);
#pragma unroll
            for (int j = 0; j < PX; j++) bests[j] = bi;
        } else {
            float bm0 = 3.4e38f, bm1 = 3.4e38f, bm2 = 3.4e38f, bm3 = 3.4e38f;
            float bf0 = 0.0f, bf1 = 0.0f, bf2 = 0.0f, bf3 = 0.0f;
            int i = 0;
            for (; i + 2 <= nsurv; i += 2) {      // unroll x2, s0 before s1
                float4 s0 = sh_surv[w][i];
                float4 s1 = sh_surv[w][i + 1];
                float  a2 = fmaf(rf, s0.y, s0.x);
                float  b2 = fmaf(rf, s1.y, s1.x);
                float  a0 = fmaf(cfs[0], s0.z, a2);
                float  a1 = fmaf(cfs[1], s0.z, a2);
                float  a22 = fmaf(cfs[2], s0.z, a2);
                float  a3 = fmaf(cfs[3], s0.z, a2);
                float  c0 = fmaf(cfs[0], s1.z, b2);
                float  c1 = fmaf(cfs[1], s1.z, b2);
                float  c2 = fmaf(cfs[2], s1.z, b2);
                float  c3 = fmaf(cfs[3], s1.z, b2);
                if (a0 < bm0) { bm0 = a0; bf0 = s0.w; }
                if (a1 < bm1) { bm1 = a1; bf1 = s0.w; }
                if (a22 < bm2) { bm2 = a22; bf2 = s0.w; }
                if (a3 < bm3) { bm3 = a3; bf3 = s0.w; }
                if (c0 < bm0) { bm0 = c0; bf0 = s1.w; }
                if (c1 < bm1) { bm1 = c1; bf1 = s1.w; }
                if (c2 < bm2) { bm2 = c2; bf2 = s1.w; }
                if (c3 < bm3) { bm3 = c3; bf3 = s1.w; }
            }
            if (i < nsurv) {
                float4 s0 = sh_surv[w][i];
                float  a2 = fmaf(rf, s0.y, s0.x);
                float  a0 = fmaf(cfs[0], s0.z, a2);
                float  a1 = fmaf(cfs[1], s0.z, a2);
                float  a22 = fmaf(cfs[2], s0.z, a2);
                float  a3 = fmaf(cfs[3], s0.z, a2);
                if (a0 < bm0) { bm0 = a0; bf0 = s0.w; }
                if (a1 < bm1) { bm1 = a1; bf1 = s0.w; }
                if (a22 < bm2) { bm2 = a22; bf2 = s0.w; }
                if (a3 < bm3) { bm3 = a3; bf3 = s0.w; }
            }
            bests[0] = __float_as_int(bf0);
            bests[1] = __float_as_int(bf1);
            bests[2] = __float_as_int(bf2);
            bests[3] = __float_as_int(bf3);
        }

        // ---- epilogue: exact d2 for winners, run-combined shared atomics ----
        int   curBest = -1;
        float ws = 0.0f, wc = 0.0f;
#pragma unroll
        for (int j = 0; j < PX; j++) {
            int    best = bests[j];
            float2 p    = sh_pos[best];
            float  dr   = rf - p.x;
            float  dc   = cfs[j] - p.y;
            float  d2   = fmaf(dr, dr, dc * dc);
            float  wgt  = heats[j] * fminf(1.0f, rsqrtf(d2));

            if (best == curBest) {
                ws += wgt;
                wc  = fmaf(wgt, cfs[j], wc);
            } else {
                if (curBest >= 0) {
                    atomicAdd(&sacc[2 * curBest],     ws * rf);
                    atomicAdd(&sacc[2 * curBest + 1], wc);
                }
                curBest = best;
                ws = wgt;
                wc = wgt * cfs[j];
            }
        }
        atomicAdd(&sacc[2 * curBest],     ws * rf);
        atomicAdd(&sacc[2 * curBest + 1], wc);

        __syncwarp();   // sh_surv reused next tile (warp-private rows)
    }

    __syncthreads();
    // per-CTA flush into one of NPART partial buffers
    const int pp = blockIdx.x & (NPART - 1);
    atomicAdd(&part[pp * (CC * 2) + t], sacc[t]);
}

extern "C" void kernel_launch(void* const* d_in, const int* in_sizes, int n_in,
                              void* d_out, int out_size)
{
    const float* clusters = (const float*)d_in[0];
    const float* heat     = (const float*)d_in[1];
    if (in_sizes[0] != CC * 2) {  // robustness to metadata order
        const float* tmp = clusters; clusters = heat; heat = tmp;
    }

    float* part = nullptr;
    float* pos  = nullptr;
    cudaGetSymbolAddress((void**)&part, g_part);
    cudaGetSymbolAddress((void**)&pos,  g_pos);
    float* out = (float*)d_out;

    for (int it = 0; it < NITER; it++) {
        float* cur = part + (it & 1) * NPART * (CC * 2);
        if (it == 0) {
            prep_kernel<<<1, TPB>>>(clusters, 1, pos, cur);
        } else {
            float* prev = part + ((it - 1) & 1) * NPART * (CC * 2);
            prep_kernel<<<1, TPB>>>(prev, NPART, pos, cur);
        }
        kmeans_iter_kernel<<<GRID, TPB>>>(pos, heat, cur);
    }
    final_kernel<<<1, TPB>>>(part + ((NITER - 1) & 1) * NPART * (CC * 2), out);
}

// round 12
// speedup vs baseline: 1.1154x; 1.1154x over previous
#include <cuda_runtime.h>

// KMeansProbSampler: 8 iterations of weighted k-means scatter on a 1024x1024
// heatmap with 128 clusters.
//
// R11 = R6-config main kernel (grid 1024, 1 tile/CTA — fastest wall-clock
// config measured) with ALL inter-iteration tiny kernels removed:
//   - main kernel inlines the 16-partial reduction of the previous
//     iteration's scatter buffer at CTA start (iter 0 reads clusters, whose
//     flattened [C,2] layout equals the 256-float reduced vector),
//   - each iteration scatters into its own pre-zeroed buffer set g_part[it]
//     (one zero kernel at sequence start zeroes all 8 sets -> replay-safe),
//   - launches: 1 zero + 8 main + 1 final = 10 (was 17).
//
// Math core (unchanged, rel_err ~2e-4):
//   key_k(r,c) = fmaf(c, -2cc_k, fmaf(r, -2cr_k, n_k)), n_k = cr^2+cc^2
//   (shifted squared distance; argmin-invariant shift; linear in r,c and fma
//   is correctly rounded -> rectangle min/max at the 4 corners with the
//   identical fmaf composition as the scan).
// Per warp (8x16 sub-tile of a 32x32 tile): corner keys per cluster,
//   UB = min_k max_corner -> keep k iff min_corner <= UB (winner+ties kept),
//   ballot-compact ascending; per-pixel scan strict '<' ascending (lowest
//   index on ties = argmin). Exact d2 for winner; w = h*min(1,rsqrt(d2)).
//   Run-combined shared atomics; per-CTA flush into 1 of 16 partials.

#define HH 1024
#define WW 1024
#define CC 128
#define NITER 8
#define PX 4
#define TPB 256
#define NWARP (TPB / 32)
#define BT 32
#define NPART 16
#define PBUF (CC * 2)                      // 256 floats per partial

__device__ float g_part[NITER][NPART][PBUF];   // per-iteration scatter sets

// zero all NITER scatter sets (start of every launch sequence / replay)
__global__ void zero_all_kernel() {
    float4* z4 = reinterpret_cast<float4*>(&g_part[0][0][0]);
    z4[blockIdx.x * TPB + threadIdx.x] = make_float4(0.f, 0.f, 0.f, 0.f);
}
#define ZERO_GRID (NITER * NPART * PBUF / 4 / TPB)   // 32 CTAs

__global__ void final_kernel(const float* __restrict__ src,
                             float* __restrict__ out)
{
    const int t = threadIdx.x;
    float s = 0.0f;
#pragma unroll
    for (int p = 0; p < NPART; p++) s += src[p * PBUF + t];
    out[t] = s;
}

__global__ __launch_bounds__(TPB) void kmeans_iter_kernel(
    const float* __restrict__ pos_src,    // [npart][256] (or clusters if npart==1)
    const int npart,
    const float* __restrict__ heat,       // [H,W]
    float* __restrict__ part)             // [NPART][256] scatter target (zeroed)
{
    __shared__ __align__(16) float4 sh_surv[NWARP][CC];  // (n,-2cr,-2cc,idx)
    __shared__ __align__(8) float sposf[PBUF];           // reduced positions
    __shared__ float sacc[PBUF];

    const int t    = threadIdx.x;
    const int w    = t >> 5;
    const int lane = t & 31;

    // inline reduction of previous iteration's partials (L2-resident)
    {
        float s = pos_src[t];
        for (int p = 1; p < npart; p++) s += pos_src[p * PBUF + t];
        sposf[t] = s;
    }
    sacc[t] = 0.0f;
    __syncthreads();

    const float2* sh_pos = reinterpret_cast<const float2*>(sposf);

    const int r0 = blockIdx.y * BT;
    const int c0 = blockIdx.x * BT;
    const int wr0 = r0 + (w >> 1) * 8;         // warp 8x16 sub-tile
    const int wc0 = c0 + (w & 1) * 16;
    const int   prow = wr0 + (lane >> 2);
    const int   pcol = wc0 + (lane & 3) * PX;
    const float rf   = (float)prow;

    // hoist heat load: latency overlaps prune + compact
    const float4 hv = *reinterpret_cast<const float4*>(heat + prow * WW + pcol);

    // ---- per-warp 2D pruning: 4 clusters per lane ----
    const float rLo = (float)wr0, rHi = (float)(wr0 + 7);
    const float cLo = (float)wc0, cHi = (float)(wc0 + 15);

    float3 cl[4];
    float  mn[4];
    float  ubl = 3.4e38f;
#pragma unroll
    for (int q = 0; q < 4; q++) {
        float2 p   = sh_pos[lane + 32 * q];
        float  n   = fmaf(p.x, p.x, p.y * p.y);
        float  m2r = -2.0f * p.x;
        float  m2c = -2.0f * p.y;
        cl[q] = make_float3(n, m2r, m2c);
        float bLo = fmaf(rLo, m2r, n);
        float bHi = fmaf(rHi, m2r, n);
        float k00 = fmaf(cLo, m2c, bLo);
        float k01 = fmaf(cHi, m2c, bLo);
        float k10 = fmaf(cLo, m2c, bHi);
        float k11 = fmaf(cHi, m2c, bHi);
        mn[q]     = fminf(fminf(k00, k01), fminf(k10, k11));
        float mx  = fmaxf(fmaxf(k00, k01), fmaxf(k10, k11));
        ubl = fminf(ubl, mx);
    }
    float ub = ubl;
#pragma unroll
    for (int off = 16; off; off >>= 1)
        ub = fminf(ub, __shfl_xor_sync(0xffffffffu, ub, off));

    int base = 0;
#pragma unroll
    for (int q = 0; q < 4; q++) {                 // ascending q, ascending lane
        bool     p   = (mn[q] <= ub);             // non-strict: ties survive
        unsigned bal = __ballot_sync(0xffffffffu, p);
        int      pos = base + __popc(bal & ((1u << lane) - 1u));
        if (p) {
            sh_surv[w][pos] = make_float4(cl[q].x, cl[q].y, cl[q].z,
                                          __int_as_float(lane + 32 * q));
        }
        base += __popc(bal);
    }
    const int nsurv = base;
    __syncwarp();

    // ---- per-pixel scan over survivors ----
    const float cf0 = (float)pcol;
    const float cfs[PX] = {cf0, cf0 + 1.0f, cf0 + 2.0f, cf0 + 3.0f};
    const float heats[PX] = {hv.x, hv.y, hv.z, hv.w};

    float bm0 = 3.4e38f, bm1 = 3.4e38f, bm2 = 3.4e38f, bm3 = 3.4e38f;
    float bf0 = 0.0f, bf1 = 0.0f, bf2 = 0.0f, bf3 = 0.0f;
    for (int i = 0; i < nsurv; i++) {
        float4 s  = sh_surv[w][i];
        float  b2 = fmaf(rf, s.y, s.x);
        float  k0 = fmaf(cfs[0], s.z, b2);
        float  k1 = fmaf(cfs[1], s.z, b2);
        float  k2 = fmaf(cfs[2], s.z, b2);
        float  k3 = fmaf(cfs[3], s.z, b2);
        if (k0 < bm0) { bm0 = k0; bf0 = s.w; }   // strict '<': lowest idx wins
        if (k1 < bm1) { bm1 = k1; bf1 = s.w; }
        if (k2 < bm2) { bm2 = k2; bf2 = s.w; }
        if (k3 < bm3) { bm3 = k3; bf3 = s.w; }
    }
    const int bests[PX] = { __float_as_int(bf0), __float_as_int(bf1),
                            __float_as_int(bf2), __float_as_int(bf3) };

    // ---- epilogue: exact d2 for winners, run-combined shared atomics ----
    int   curBest = -1;
    float ws = 0.0f, wc = 0.0f;
#pragma unroll
    for (int j = 0; j < PX; j++) {
        int    best = bests[j];
        float2 p    = sh_pos[best];
        float  dr   = rf - p.x;
        float  dc   = cfs[j] - p.y;
        float  d2   = fmaf(dr, dr, dc * dc);
        float  wgt  = heats[j] * fminf(1.0f, rsqrtf(d2));

        if (best == curBest) {
            ws += wgt;
            wc  = fmaf(wgt, cfs[j], wc);
        } else {
            if (curBest >= 0) {
                atomicAdd(&sacc[2 * curBest],     ws * rf);
                atomicAdd(&sacc[2 * curBest + 1], wc);
            }
            curBest = best;
            ws = wgt;
            wc = wgt * cfs[j];
        }
    }
    atomicAdd(&sacc[2 * curBest],     ws * rf);
    atomicAdd(&sacc[2 * curBest + 1], wc);

    __syncthreads();
    // per-CTA flush into one of NPART partial buffers (fan-in 64 per address)
    const int pp = (blockIdx.y * (WW / BT) + blockIdx.x) & (NPART - 1);
    atomicAdd(&part[pp * PBUF + t], sacc[t]);
}

extern "C" void kernel_launch(void* const* d_in, const int* in_sizes, int n_in,
                              void* d_out, int out_size)
{
    const float* clusters = (const float*)d_in[0];
    const float* heat     = (const float*)d_in[1];
    if (in_sizes[0] != CC * 2) {  // robustness to metadata order
        const float* tmp = clusters; clusters = heat; heat = tmp;
    }

    float* part = nullptr;
    cudaGetSymbolAddress((void**)&part, g_part);
    float* out = (float*)d_out;

    zero_all_kernel<<<ZERO_GRID, TPB>>>();

    dim3 grid(WW / BT, HH / BT);
    for (int it = 0; it < NITER; it++) {
        const float* src = (it == 0) ? clusters
                                     : part + (it - 1) * NPART * PBUF;
        const int npart  = (it == 0) ? 1 : NPART;
        float* cur = part + it * NPART * PBUF;
        kmeans_iter_kernel<<<grid, TPB>>>(src, npart, heat, cur);
    }
    final_kernel<<<1, TPB>>>(part + (NITER - 1) * NPART * PBUF, out);
}

// round 13
// speedup vs baseline: 1.5256x; 1.3678x over previous
#include <cuda_runtime.h>

// KMeansProbSampler: 8 iterations of weighted k-means scatter on a 1024x1024
// heatmap with 128 clusters.
//
// R13: exact single-wave geometry, minimal launch chain.
//   - TPB=128 (4 warps), PX=8 pixels/thread, grid = 32x32 tiles (1024 CTAs).
//     8 CTAs/SM x 4 warps = 32 warps = full occupancy; 1024 CTAs fit in ONE
//     wave (no wave-quantization tail). __launch_bounds__(128,8).
//   - Each iteration scatters (RED) directly into the next iteration's
//     256-float position buffer (fan-in 1024/address measured free in R6/R9);
//     next kernel loads it with one LDG per thread. No partials/prep/final.
//   - Launches: 1 zero (re-zeroes all buffers + d_out -> replay-safe)
//     + 8 main = 9.
//
// Math core (unchanged, rel_err ~2e-4):
//   key_k(r,c) = fmaf(c, -2cc_k, fmaf(r, -2cr_k, n_k)), n_k = cr^2+cc^2
//   (shifted squared distance; argmin-invariant shift; linear in r,c and fma
//   is correctly rounded -> rectangle min/max at the 4 corners with the
//   identical fmaf composition as the scan).
// Per warp (8x32 strip of a 32x32 tile): corner keys per cluster,
//   UB = min_k max_corner -> keep k iff min_corner <= UB (winner+ties kept),
//   ballot-compact ascending; per-pixel scan strict '<' ascending (lowest
//   index on ties = argmin). Exact d2 for winner; w = h*min(1,rsqrt(d2)).
//   Run-combined shared atomics; per-CTA flush (256 REDs).

#define HH 1024
#define WW 1024
#define CC 128
#define NITER 8
#define PX 8
#define TPB 128
#define NWARP (TPB / 32)
#define BT 32

__device__ float g_next[NITER - 1][CC * 2];   // inter-iteration position sums

// zero all inter-iteration buffers + d_out (start of every replay)
__global__ void zero_kernel(float* __restrict__ out) {
    const int t = threadIdx.x;    // 256 threads
    out[t] = 0.0f;
#pragma unroll
    for (int i = 0; i < NITER - 1; i++) g_next[i][t] = 0.0f;
}

__global__ __launch_bounds__(TPB, 8) void kmeans_iter_kernel(
    const float* __restrict__ pos_src,    // [256] position sums (or clusters)
    const float* __restrict__ heat,       // [H,W]
    float* __restrict__ nxt)              // [256] scatter target (pre-zeroed)
{
    __shared__ __align__(16) float4 sh_surv[NWARP][CC];  // (n,-2cr,-2cc,idx)
    __shared__ __align__(8) float sposf[CC * 2];
    __shared__ float sacc[CC * 2];

    const int t    = threadIdx.x;
    const int w    = t >> 5;
    const int lane = t & 31;

    sposf[t]       = pos_src[t];
    sposf[t + TPB] = pos_src[t + TPB];
    sacc[t]        = 0.0f;
    sacc[t + TPB]  = 0.0f;
    __syncthreads();

    const float2* sh_pos = reinterpret_cast<const float2*>(sposf);

    const int r0  = blockIdx.y * BT;
    const int c0  = blockIdx.x * BT;
    const int wr0 = r0 + w * 8;                 // warp strip: 8 rows x 32 cols
    const int   prow = wr0 + (lane >> 2);
    const int   pcol = c0 + (lane & 3) * PX;
    const float rf   = (float)prow;

    // hoist heat loads: latency overlaps prune + compact
    const float4 hv0 = *reinterpret_cast<const float4*>(heat + prow * WW + pcol);
    const float4 hv1 = *reinterpret_cast<const float4*>(heat + prow * WW + pcol + 4);

    // ---- per-warp 2D pruning over the 8x32 strip: 4 clusters per lane ----
    const float rLo = (float)wr0, rHi = (float)(wr0 + 7);
    const float cLo = (float)c0,  cHi = (float)(c0 + BT - 1);

    float3 cl[4];
    float  mn[4];
    float  ubl = 3.4e38f;
#pragma unroll
    for (int q = 0; q < 4; q++) {
        float2 p   = sh_pos[lane + 32 * q];
        float  n   = fmaf(p.x, p.x, p.y * p.y);
        float  m2r = -2.0f * p.x;
        float  m2c = -2.0f * p.y;
        cl[q] = make_float3(n, m2r, m2c);
        float bLo = fmaf(rLo, m2r, n);
        float bHi = fmaf(rHi, m2r, n);
        float k00 = fmaf(cLo, m2c, bLo);
        float k01 = fmaf(cHi, m2c, bLo);
        float k10 = fmaf(cLo, m2c, bHi);
        float k11 = fmaf(cHi, m2c, bHi);
        mn[q]     = fminf(fminf(k00, k01), fminf(k10, k11));
        float mx  = fmaxf(fmaxf(k00, k01), fmaxf(k10, k11));
        ubl = fminf(ubl, mx);
    }
    float ub = ubl;
#pragma unroll
    for (int off = 16; off; off >>= 1)
        ub = fminf(ub, __shfl_xor_sync(0xffffffffu, ub, off));

    int base = 0;
#pragma unroll
    for (int q = 0; q < 4; q++) {                 // ascending q, ascending lane
        bool     p   = (mn[q] <= ub);             // non-strict: ties survive
        unsigned bal = __ballot_sync(0xffffffffu, p);
        int      pos = base + __popc(bal & ((1u << lane) - 1u));
        if (p) {
            sh_surv[w][pos] = make_float4(cl[q].x, cl[q].y, cl[q].z,
                                          __int_as_float(lane + 32 * q));
        }
        base += __popc(bal);
    }
    const int nsurv = base;
    __syncwarp();

    // ---- per-pixel scan over survivors (8 pixels/thread) ----
    const float cf0 = (float)pcol;
    float cfs[PX];
#pragma unroll
    for (int j = 0; j < PX; j++) cfs[j] = cf0 + (float)j;
    const float heats[PX] = {hv0.x, hv0.y, hv0.z, hv0.w,
                             hv1.x, hv1.y, hv1.z, hv1.w};

    float bm[PX], bf[PX];
#pragma unroll
    for (int j = 0; j < PX; j++) { bm[j] = 3.4e38f; bf[j] = 0.0f; }

    for (int i = 0; i < nsurv; i++) {
        float4 s  = sh_surv[w][i];
        float  b2 = fmaf(rf, s.y, s.x);
#pragma unroll
        for (int j = 0; j < PX; j++) {
            float k = fmaf(cfs[j], s.z, b2);
            if (k < bm[j]) { bm[j] = k; bf[j] = s.w; }  // strict '<': lowest idx
        }
    }

    // ---- epilogue: exact d2 for winners, run-combined shared atomics ----
    int   curBest = -1;
    float ws = 0.0f, wc = 0.0f;
#pragma unroll
    for (int j = 0; j < PX; j++) {
        int    best = __float_as_int(bf[j]);
        float2 p    = sh_pos[best];
        float  dr   = rf - p.x;
        float  dc   = cfs[j] - p.y;
        float  d2   = fmaf(dr, dr, dc * dc);
        float  wgt  = heats[j] * fminf(1.0f, rsqrtf(d2));

        if (best == curBest) {
            ws += wgt;
            wc  = fmaf(wgt, cfs[j], wc);
        } else {
            if (curBest >= 0) {
                atomicAdd(&sacc[2 * curBest],     ws * rf);
                atomicAdd(&sacc[2 * curBest + 1], wc);
            }
            curBest = best;
            ws = wgt;
            wc = wgt * cfs[j];
        }
    }
    atomicAdd(&sacc[2 * curBest],     ws * rf);
    atomicAdd(&sacc[2 * curBest + 1], wc);

    __syncthreads();
    // direct flush into next iteration's position buffer (RED, fan-in 1024)
    atomicAdd(&nxt[t],       sacc[t]);
    atomicAdd(&nxt[t + TPB], sacc[t + TPB]);
}

extern "C" void kernel_launch(void* const* d_in, const int* in_sizes, int n_in,
                              void* d_out, int out_size)
{
    const float* clusters = (const float*)d_in[0];
    const float* heat     = (const float*)d_in[1];
    if (in_sizes[0] != CC * 2) {  // robustness to metadata order
        const float* tmp = clusters; clusters = heat; heat = tmp;
    }

    float* nxt0 = nullptr;
    cudaGetSymbolAddress((void**)&nxt0, g_next);
    float* out = (float*)d_out;

    zero_kernel<<<1, CC * 2>>>(out);

    dim3 grid(WW / BT, HH / BT);
    for (int it = 0; it < NITER; it++) {
        const float* src = (it == 0) ? clusters : (nxt0 + (it - 1) * CC * 2);
        float*       dst = (it == NITER - 1) ? out : (nxt0 + it * CC * 2);
        kmeans_iter_kernel<<<grid, TPB>>>(src, heat, dst);
    }
}